// round 1
// baseline (speedup 1.0000x reference)
#include <cuda_runtime.h>
#include <math.h>

#define N_NODES 50000
#define N_EDGES 800000
#define NFEAT   256
#define NHID    64
#define NCLASS  40
#define LOGSM_OFF (N_NODES * NCLASS)

// Scratch (static __device__ — no allocations allowed)
__device__ float g_A[N_NODES * NHID];      // x @ W1
__device__ float g_hacc[N_NODES * NHID];   // spmm1 accumulator
__device__ float g_B[N_NODES * NCLASS];    // relu(hacc+b1) @ W2
__device__ float g_lacc[N_NODES * NCLASS]; // spmm2 accumulator

// ---------------------------------------------------------------------------
// Zero both accumulators (must run every launch — graph replays reuse state)
// ---------------------------------------------------------------------------
__global__ void zero_acc_kernel() {
    int i = blockIdx.x * blockDim.x + threadIdx.x;
    float4 z = make_float4(0.f, 0.f, 0.f, 0.f);
    if (i < (N_NODES * NHID) / 4)   ((float4*)g_hacc)[i] = z;
    if (i < (N_NODES * NCLASS) / 4) ((float4*)g_lacc)[i] = z;
}

// ---------------------------------------------------------------------------
// GEMM1: g_A = x @ W1   [50000,256] @ [256,64]
// 2 nodes per thread; W1 staged in smem in two 128-row phases (32KB static).
// ---------------------------------------------------------------------------
__global__ __launch_bounds__(128) void gemm1_kernel(const float* __restrict__ x,
                                                    const float* __restrict__ W1) {
    __shared__ float W1s[128 * NHID]; // 32 KB: rows [ph*128, ph*128+128)

    int tid = blockIdx.x * 128 + threadIdx.x;
    int node0 = tid * 2;
    bool valid = (node0 < N_NODES);
    int n0 = valid ? node0 : 0;
    int n1 = n0 + 1;

    float4 acc0[16], acc1[16];
#pragma unroll
    for (int j = 0; j < 16; j++) {
        acc0[j] = make_float4(0.f, 0.f, 0.f, 0.f);
        acc1[j] = make_float4(0.f, 0.f, 0.f, 0.f);
    }

    const float4* xv = (const float4*)x;

    for (int ph = 0; ph < 2; ph++) {
        __syncthreads();
        // Cooperative load of 128 rows of W1 (128*64 floats = 2048 float4)
        {
            const float4* Wg = (const float4*)(W1 + ph * 128 * NHID);
            float4* Ws = (float4*)W1s;
            for (int i = threadIdx.x; i < (128 * NHID) / 4; i += 128)
                Ws[i] = Wg[i];
        }
        __syncthreads();

        int kbase = ph * 128;
#pragma unroll 4
        for (int kk = 0; kk < 128; kk += 4) {
            float4 xa = xv[n0 * (NFEAT / 4) + (kbase + kk) / 4];
            float4 xb = xv[n1 * (NFEAT / 4) + (kbase + kk) / 4];
            float xs0[4] = {xa.x, xa.y, xa.z, xa.w};
            float xs1[4] = {xb.x, xb.y, xb.z, xb.w};
#pragma unroll
            for (int u = 0; u < 4; u++) {
                const float4* wrow = (const float4*)(W1s + (kk + u) * NHID);
                float v0 = xs0[u], v1 = xs1[u];
#pragma unroll
                for (int jj = 0; jj < 16; jj++) {
                    float4 w = wrow[jj];
                    acc0[jj].x += v0 * w.x; acc0[jj].y += v0 * w.y;
                    acc0[jj].z += v0 * w.z; acc0[jj].w += v0 * w.w;
                    acc1[jj].x += v1 * w.x; acc1[jj].y += v1 * w.y;
                    acc1[jj].z += v1 * w.z; acc1[jj].w += v1 * w.w;
                }
            }
        }
    }

    if (valid) {
        float4* out = (float4*)g_A;
#pragma unroll
        for (int jj = 0; jj < 16; jj++) {
            out[n0 * 16 + jj] = acc0[jj];
            out[n1 * 16 + jj] = acc1[jj];
        }
    }
}

// ---------------------------------------------------------------------------
// SpMM1: g_hacc[dst] += g_A[src] * w   (16 threads per edge, float4 gathers)
// ---------------------------------------------------------------------------
__global__ void spmm1_kernel(const float* __restrict__ ew,
                             const int* __restrict__ esrc,
                             const int* __restrict__ edst) {
    int gid = blockIdx.x * blockDim.x + threadIdx.x;
    int e = gid >> 4;
    if (e >= N_EDGES) return;
    int q = gid & 15;

    int s = __ldg(&esrc[e]);
    int d = __ldg(&edst[e]);
    float w = __ldg(&ew[e]);

    float4 a = ((const float4*)g_A)[s * 16 + q];
    float* dstp = &g_hacc[d * NHID + q * 4];
    atomicAdd(dstp + 0, a.x * w);
    atomicAdd(dstp + 1, a.y * w);
    atomicAdd(dstp + 2, a.z * w);
    atomicAdd(dstp + 3, a.w * w);
}

// ---------------------------------------------------------------------------
// Layer2: h = relu(g_hacc + b1); g_B = h @ W2   (one node per thread)
// ---------------------------------------------------------------------------
__global__ __launch_bounds__(128) void layer2_kernel(const float* __restrict__ b1,
                                                     const float* __restrict__ W2) {
    __shared__ float W2s[NHID * NCLASS]; // 10 KB
    __shared__ float b1s[NHID];

    for (int i = threadIdx.x; i < NHID * NCLASS; i += 128) W2s[i] = W2[i];
    if (threadIdx.x < NHID) b1s[threadIdx.x] = b1[threadIdx.x];
    __syncthreads();

    int node = blockIdx.x * 128 + threadIdx.x;
    if (node >= N_NODES) return;

    float4 acc[10];
#pragma unroll
    for (int j = 0; j < 10; j++) acc[j] = make_float4(0.f, 0.f, 0.f, 0.f);

    const float4* hin = (const float4*)(g_hacc + node * NHID);
#pragma unroll 4
    for (int k4 = 0; k4 < 16; k4++) {
        float4 hv = hin[k4];
        float hs[4] = {hv.x, hv.y, hv.z, hv.w};
#pragma unroll
        for (int u = 0; u < 4; u++) {
            int k = k4 * 4 + u;
            float h = hs[u] + b1s[k];
            h = fmaxf(h, 0.f);
            const float4* wrow = (const float4*)(W2s + k * NCLASS);
#pragma unroll
            for (int jj = 0; jj < 10; jj++) {
                float4 w = wrow[jj];
                acc[jj].x += h * w.x; acc[jj].y += h * w.y;
                acc[jj].z += h * w.z; acc[jj].w += h * w.w;
            }
        }
    }

    float4* out = (float4*)(g_B + node * NCLASS);
#pragma unroll
    for (int jj = 0; jj < 10; jj++) out[jj] = acc[jj];
}

// ---------------------------------------------------------------------------
// SpMM2: g_lacc[dst] += g_B[src] * w   (10 threads per edge, float4 gathers)
// ---------------------------------------------------------------------------
__global__ void spmm2_kernel(const float* __restrict__ ew,
                             const int* __restrict__ esrc,
                             const int* __restrict__ edst) {
    int gid = blockIdx.x * blockDim.x + threadIdx.x;
    int e = gid / 10;
    if (e >= N_EDGES) return;
    int q = gid - e * 10;

    int s = __ldg(&esrc[e]);
    int d = __ldg(&edst[e]);
    float w = __ldg(&ew[e]);

    float4 a = ((const float4*)g_B)[s * 10 + q];
    float* dstp = &g_lacc[d * NCLASS + q * 4];
    atomicAdd(dstp + 0, a.x * w);
    atomicAdd(dstp + 1, a.y * w);
    atomicAdd(dstp + 2, a.z * w);
    atomicAdd(dstp + 3, a.w * w);
}

// ---------------------------------------------------------------------------
// Finalize: logits = g_lacc + b2; out[0:2M]=logits, out[2M:4M]=log_softmax
// ---------------------------------------------------------------------------
__global__ __launch_bounds__(128) void finalize_kernel(const float* __restrict__ b2,
                                                       float* __restrict__ out) {
    __shared__ float b2s[NCLASS];
    if (threadIdx.x < NCLASS) b2s[threadIdx.x] = b2[threadIdx.x];
    __syncthreads();

    int node = blockIdx.x * 128 + threadIdx.x;
    if (node >= N_NODES) return;

    float v[NCLASS];
    float mx = -INFINITY;
    const float4* lin = (const float4*)(g_lacc + node * NCLASS);
#pragma unroll
    for (int jj = 0; jj < 10; jj++) {
        float4 a = lin[jj];
        v[jj * 4 + 0] = a.x + b2s[jj * 4 + 0];
        v[jj * 4 + 1] = a.y + b2s[jj * 4 + 1];
        v[jj * 4 + 2] = a.z + b2s[jj * 4 + 2];
        v[jj * 4 + 3] = a.w + b2s[jj * 4 + 3];
    }
#pragma unroll
    for (int j = 0; j < NCLASS; j++) mx = fmaxf(mx, v[j]);
    float s = 0.f;
#pragma unroll
    for (int j = 0; j < NCLASS; j++) s += expf(v[j] - mx);
    float lse = mx + logf(s);

    float4* o1 = (float4*)(out + node * NCLASS);
    float4* o2 = (float4*)(out + LOGSM_OFF + node * NCLASS);
#pragma unroll
    for (int jj = 0; jj < 10; jj++) {
        float4 a = make_float4(v[jj * 4 + 0], v[jj * 4 + 1],
                               v[jj * 4 + 2], v[jj * 4 + 3]);
        o1[jj] = a;
        float4 b = make_float4(a.x - lse, a.y - lse, a.z - lse, a.w - lse);
        o2[jj] = b;
    }
}

// ---------------------------------------------------------------------------
extern "C" void kernel_launch(void* const* d_in, const int* in_sizes, int n_in,
                              void* d_out, int out_size) {
    const float* x   = (const float*)d_in[0];
    const float* W1  = (const float*)d_in[1];
    const float* b1  = (const float*)d_in[2];
    const float* W2  = (const float*)d_in[3];
    const float* b2  = (const float*)d_in[4];
    const float* ew  = (const float*)d_in[5];
    const int*  esrc = (const int*)d_in[6];
    const int*  edst = (const int*)d_in[7];
    float* out = (float*)d_out;

    // Zero accumulators (every call — graph replays)
    {
        int n4 = (N_NODES * NHID) / 4; // 800000 (covers lacc's 500000 too)
        zero_acc_kernel<<<(n4 + 255) / 256, 256>>>();
    }
    // GEMM1
    {
        int threads = (N_NODES + 1) / 2; // 25000
        gemm1_kernel<<<(threads + 127) / 128, 128>>>(x, W1);
    }
    // SpMM1
    {
        int total = N_EDGES * 16; // 12.8M
        spmm1_kernel<<<(total + 255) / 256, 256>>>(ew, esrc, edst);
    }
    // ReLU + bias + GEMM2
    layer2_kernel<<<(N_NODES + 127) / 128, 128>>>(b1, W2);
    // SpMM2
    {
        int total = N_EDGES * 10; // 8M
        spmm2_kernel<<<(total + 255) / 256, 256>>>(ew, esrc, edst);
    }
    // bias + log_softmax + write both outputs
    finalize_kernel<<<(N_NODES + 127) / 128, 128>>>(b2, out);
}

// round 2
// speedup vs baseline: 1.6410x; 1.6410x over previous
#include <cuda_runtime.h>
#include <math.h>

#define N_NODES 50000
#define N_EDGES 800000
#define NFEAT   256
#define NHID    64
#define NCLASS  40
#define LOGSM_OFF (N_NODES * NCLASS)

// Scratch (static __device__ — no allocations allowed)
__device__ float g_A[N_NODES * NHID];      // x @ W1
__device__ float g_hacc[N_NODES * NHID];   // spmm1 accumulator
__device__ float g_B[N_NODES * NCLASS];    // relu(hacc+b1) @ W2
__device__ float g_lacc[N_NODES * NCLASS]; // spmm2 accumulator

// ---------------------------------------------------------------------------
// Zero both accumulators (must run every launch — graph replays reuse state)
// ---------------------------------------------------------------------------
__global__ void zero_acc_kernel() {
    int i = blockIdx.x * blockDim.x + threadIdx.x;
    float4 z = make_float4(0.f, 0.f, 0.f, 0.f);
    if (i < (N_NODES * NHID) / 4)   ((float4*)g_hacc)[i] = z;
    if (i < (N_NODES * NCLASS) / 4) ((float4*)g_lacc)[i] = z;
}

// ---------------------------------------------------------------------------
// GEMM1: g_A = x @ W1   [50000,256] @ [256,64]
// 1 node per thread; W1 staged in smem in two 128-row phases (32KB static).
// ---------------------------------------------------------------------------
__global__ __launch_bounds__(128) void gemm1_kernel(const float* __restrict__ x,
                                                    const float* __restrict__ W1) {
    __shared__ float W1s[128 * NHID]; // 32 KB: rows [ph*128, ph*128+128)

    int node = blockIdx.x * 128 + threadIdx.x;
    bool valid = (node < N_NODES);
    int n0 = valid ? node : 0;

    float4 acc[16];
#pragma unroll
    for (int j = 0; j < 16; j++) acc[j] = make_float4(0.f, 0.f, 0.f, 0.f);

    const float4* xv = (const float4*)x;

    for (int ph = 0; ph < 2; ph++) {
        __syncthreads();
        {
            const float4* Wg = (const float4*)(W1 + ph * 128 * NHID);
            float4* Ws = (float4*)W1s;
            for (int i = threadIdx.x; i < (128 * NHID) / 4; i += 128)
                Ws[i] = Wg[i];
        }
        __syncthreads();

        int kbase = ph * 128;
#pragma unroll 4
        for (int kk = 0; kk < 128; kk += 4) {
            float4 xa = xv[n0 * (NFEAT / 4) + (kbase + kk) / 4];
            float xs0[4] = {xa.x, xa.y, xa.z, xa.w};
#pragma unroll
            for (int u = 0; u < 4; u++) {
                const float4* wrow = (const float4*)(W1s + (kk + u) * NHID);
                float v0 = xs0[u];
#pragma unroll
                for (int jj = 0; jj < 16; jj++) {
                    float4 w = wrow[jj];
                    acc[jj].x += v0 * w.x; acc[jj].y += v0 * w.y;
                    acc[jj].z += v0 * w.z; acc[jj].w += v0 * w.w;
                }
            }
        }
    }

    if (valid) {
        float4* out = (float4*)g_A;
#pragma unroll
        for (int jj = 0; jj < 16; jj++) out[n0 * 16 + jj] = acc[jj];
    }
}

// ---------------------------------------------------------------------------
// SpMM1: g_hacc[dst] += g_A[src] * w   (16 threads/edge, ONE float4 RED each)
// ---------------------------------------------------------------------------
__global__ void spmm1_kernel(const float* __restrict__ ew,
                             const int* __restrict__ esrc,
                             const int* __restrict__ edst) {
    int gid = blockIdx.x * blockDim.x + threadIdx.x;
    int e = gid >> 4;
    if (e >= N_EDGES) return;
    int q = gid & 15;

    int s = __ldg(&esrc[e]);
    int d = __ldg(&edst[e]);
    float w = __ldg(&ew[e]);

    float4 a = ((const float4*)g_A)[s * 16 + q];
    float4 m = make_float4(a.x * w, a.y * w, a.z * w, a.w * w);
    // sm_90+ native vector atomic: single L2 reduction op for 16 bytes
    atomicAdd((float4*)&g_hacc[d * NHID + q * 4], m);
}

// ---------------------------------------------------------------------------
// Layer2: h = relu(g_hacc + b1); g_B = h @ W2
// 2 threads per node (20 output cols each) for 2x occupancy.
// ---------------------------------------------------------------------------
__global__ __launch_bounds__(256) void layer2_kernel(const float* __restrict__ b1,
                                                     const float* __restrict__ W2) {
    __shared__ float W2s[NHID * NCLASS]; // 10 KB
    __shared__ float b1s[NHID];

    for (int i = threadIdx.x; i < NHID * NCLASS; i += 256) W2s[i] = W2[i];
    if (threadIdx.x < NHID) b1s[threadIdx.x] = b1[threadIdx.x];
    __syncthreads();

    int tid = blockIdx.x * 256 + threadIdx.x;
    int node = tid >> 1;
    int half = tid & 1;          // 0 -> cols [0,20), 1 -> cols [20,40)
    if (node >= N_NODES) return;
    int cbase = half * 20;

    float4 acc[5];
#pragma unroll
    for (int j = 0; j < 5; j++) acc[j] = make_float4(0.f, 0.f, 0.f, 0.f);

    const float4* hin = (const float4*)(g_hacc + node * NHID);
#pragma unroll 4
    for (int k4 = 0; k4 < 16; k4++) {
        float4 hv = hin[k4];
        float hs[4] = {hv.x, hv.y, hv.z, hv.w};
#pragma unroll
        for (int u = 0; u < 4; u++) {
            int k = k4 * 4 + u;
            float h = fmaxf(hs[u] + b1s[k], 0.f);
            const float4* wrow = (const float4*)(W2s + k * NCLASS + cbase);
#pragma unroll
            for (int jj = 0; jj < 5; jj++) {
                float4 w = wrow[jj];
                acc[jj].x += h * w.x; acc[jj].y += h * w.y;
                acc[jj].z += h * w.z; acc[jj].w += h * w.w;
            }
        }
    }

    float4* out = (float4*)(g_B + node * NCLASS + cbase);
#pragma unroll
    for (int jj = 0; jj < 5; jj++) out[jj] = acc[jj];
}

// ---------------------------------------------------------------------------
// SpMM2: g_lacc[dst] += g_B[src] * w   (10 threads/edge, ONE float4 RED each)
// ---------------------------------------------------------------------------
__global__ void spmm2_kernel(const float* __restrict__ ew,
                             const int* __restrict__ esrc,
                             const int* __restrict__ edst) {
    int gid = blockIdx.x * blockDim.x + threadIdx.x;
    int e = gid / 10;
    if (e >= N_EDGES) return;
    int q = gid - e * 10;

    int s = __ldg(&esrc[e]);
    int d = __ldg(&edst[e]);
    float w = __ldg(&ew[e]);

    float4 a = ((const float4*)g_B)[s * 10 + q];
    float4 m = make_float4(a.x * w, a.y * w, a.z * w, a.w * w);
    atomicAdd((float4*)&g_lacc[d * NCLASS + q * 4], m);
}

// ---------------------------------------------------------------------------
// Finalize: logits = g_lacc + b2; out[0:2M]=logits, out[2M:4M]=log_softmax
// ---------------------------------------------------------------------------
__global__ __launch_bounds__(128) void finalize_kernel(const float* __restrict__ b2,
                                                       float* __restrict__ out) {
    __shared__ float b2s[NCLASS];
    if (threadIdx.x < NCLASS) b2s[threadIdx.x] = b2[threadIdx.x];
    __syncthreads();

    int node = blockIdx.x * 128 + threadIdx.x;
    if (node >= N_NODES) return;

    float v[NCLASS];
    float mx = -INFINITY;
    const float4* lin = (const float4*)(g_lacc + node * NCLASS);
#pragma unroll
    for (int jj = 0; jj < 10; jj++) {
        float4 a = lin[jj];
        v[jj * 4 + 0] = a.x + b2s[jj * 4 + 0];
        v[jj * 4 + 1] = a.y + b2s[jj * 4 + 1];
        v[jj * 4 + 2] = a.z + b2s[jj * 4 + 2];
        v[jj * 4 + 3] = a.w + b2s[jj * 4 + 3];
    }
#pragma unroll
    for (int j = 0; j < NCLASS; j++) mx = fmaxf(mx, v[j]);
    float s = 0.f;
#pragma unroll
    for (int j = 0; j < NCLASS; j++) s += expf(v[j] - mx);
    float lse = mx + logf(s);

    float4* o1 = (float4*)(out + node * NCLASS);
    float4* o2 = (float4*)(out + LOGSM_OFF + node * NCLASS);
#pragma unroll
    for (int jj = 0; jj < 10; jj++) {
        float4 a = make_float4(v[jj * 4 + 0], v[jj * 4 + 1],
                               v[jj * 4 + 2], v[jj * 4 + 3]);
        o1[jj] = a;
        float4 b = make_float4(a.x - lse, a.y - lse, a.z - lse, a.w - lse);
        o2[jj] = b;
    }
}

// ---------------------------------------------------------------------------
extern "C" void kernel_launch(void* const* d_in, const int* in_sizes, int n_in,
                              void* d_out, int out_size) {
    const float* x   = (const float*)d_in[0];
    const float* W1  = (const float*)d_in[1];
    const float* b1  = (const float*)d_in[2];
    const float* W2  = (const float*)d_in[3];
    const float* b2  = (const float*)d_in[4];
    const float* ew  = (const float*)d_in[5];
    const int*  esrc = (const int*)d_in[6];
    const int*  edst = (const int*)d_in[7];
    float* out = (float*)d_out;

    // Zero accumulators (every call — graph replays)
    {
        int n4 = (N_NODES * NHID) / 4; // 800000 (covers lacc's 500000 too)
        zero_acc_kernel<<<(n4 + 255) / 256, 256>>>();
    }
    // GEMM1
    gemm1_kernel<<<(N_NODES + 127) / 128, 128>>>(x, W1);
    // SpMM1 (vector RED)
    {
        int total = N_EDGES * 16; // 12.8M
        spmm1_kernel<<<(total + 255) / 256, 256>>>(ew, esrc, edst);
    }
    // ReLU + bias + GEMM2 (2 threads/node)
    {
        int total = N_NODES * 2;
        layer2_kernel<<<(total + 255) / 256, 256>>>(b1, W2);
    }
    // SpMM2 (vector RED)
    {
        int total = N_EDGES * 10; // 8M
        spmm2_kernel<<<(total + 255) / 256, 256>>>(ew, esrc, edst);
    }
    // bias + log_softmax + write both outputs
    finalize_kernel<<<(N_NODES + 127) / 128, 128>>>(b2, out);
}